// round 5
// baseline (speedup 1.0000x reference)
#include <cuda_runtime.h>

// Problem constants
#define GAMMA 0.1f
#define TAU   0.01f
#define NN    256          // neuron count
#define MM    512          // astrocyte count
#define KK    512          // input dim
#define NN2   (NN * NN)    // 65536
#define SPLIT 16           // chunks per H row
#define CHUNK (NN2 / SPLIT) // 4096 floats per chunk

#define X_BLKS   32
#define W2_BLKS  64
#define SETUP_BLKS (X_BLKS + W2_BLKS)     // 96
#define D_BLKS   8192
#define H_BLKS   8192
#define TOTAL_BLKS (SETUP_BLKS + D_BLKS + H_BLKS)

// Scratch (no allocations allowed in kernel_launch). Zero-initialized at load;
// all counters/flags are reset in-kernel for graph replay.
__device__ float g_phi[NN];           // sigmoid(x_new)
__device__ float g_part[MM * SPLIT];  // H@Phi partial sums
__device__ float g_win2[MM];          // W_in_2 @ I
__device__ int   g_cnt[MM];           // per-row H-chunk arrival counters (self-resetting)
__device__ int   g_done_phi;          // x-block completion counter
__device__ int   g_done_w2;           // win2-block completion counter
__device__ int   g_rows;              // completed H rows (for final reset)
__device__ volatile int g_fphi;       // phi-ready flag
__device__ volatile int g_fw2;        // win2-ready flag

__device__ __forceinline__ float warp_sum(float v) {
#pragma unroll
    for (int o = 16; o > 0; o >>= 1) v += __shfl_xor_sync(0xffffffffu, v, o);
    return v;
}

__device__ __forceinline__ float sigmoidf(float v) {
    return 1.0f / (1.0f + expf(-v));
}

// ---------------------------------------------------------------------------
// Single mega-kernel: 16480 blocks x 256 threads.
//   [0, 32)        x_new + phi  -> release g_fphi     (0.78 MB, fast)
//   [32, 96)       W_in_2 @ I   -> release g_fw2      (1 MB)
//   [96, 8288)     W_new rows: D GEMV streamed; epilogue polls g_fphi (no fence)
//   [8288, 16480)  H@Phi partials; last chunk per row combines z_new
// ---------------------------------------------------------------------------
__global__ void __launch_bounds__(256) kBig(
    const float* __restrict__ x,    const float* __restrict__ W,
    const float* __restrict__ Win1, const float* __restrict__ I,
    const float* __restrict__ Win2, const float* __restrict__ C,
    const float* __restrict__ D,    const float* __restrict__ z,
    const float* __restrict__ H,    const float* __restrict__ F,
    float* __restrict__ out_x, float* __restrict__ out_W,
    float* __restrict__ out_z) {

    __shared__ float s_vec[MM];
    __shared__ float s_red[8];
    int tid  = threadIdx.x;  // 256
    int warp = tid >> 5, lane = tid & 31;
    unsigned bid = blockIdx.x;

    if (bid < X_BLKS) {
        // ================= setup: x_new + phi =================
        __shared__ float s_phi[NN];
        s_phi[tid]       = sigmoidf(x[tid]);
        s_vec[tid]       = I[tid];
        s_vec[tid + 256] = I[tid + 256];
        __syncthreads();
        int row = bid * 8 + warp;

        float a1 = 0.0f, a2 = 0.0f;
        const float* wr = W + (size_t)row * NN;
#pragma unroll
        for (int j = lane; j < NN; j += 32) a1 += wr[j] * s_phi[j];
        const float4* w1 = (const float4*)(Win1 + (size_t)row * KK);
        const float4* sI = (const float4*)s_vec;
#pragma unroll
        for (int q = 0; q < 4; q++) {
            float4 a = w1[lane + 32 * q];
            float4 b = sI[lane + 32 * q];
            a2 += a.x * b.x + a.y * b.y + a.z * b.z + a.w * b.w;
        }
        a1 = warp_sum(a1);
        a2 = warp_sum(a2);
        if (lane == 0) {
            float xn = (1.0f - GAMMA) * x[row] + GAMMA * a1 + a2;
            out_x[row] = xn;
            g_phi[row] = sigmoidf(xn);
            __threadfence();                 // publish phi (8 per block)
        }
        __syncthreads();
        if (tid == 0) {
            int old = atomicAdd(&g_done_phi, 1);
            if (old == X_BLKS - 1) { g_done_phi = 0; g_fphi = 1; }  // release
        }
    } else if (bid < SETUP_BLKS) {
        // ================= setup: W_in_2 @ I =================
        s_vec[tid]       = I[tid];
        s_vec[tid + 256] = I[tid + 256];
        __syncthreads();
        int row = (bid - X_BLKS) * 8 + warp;  // 0..511
        const float4* w2 = (const float4*)(Win2 + (size_t)row * KK);
        const float4* sI = (const float4*)s_vec;
        float acc = 0.0f;
#pragma unroll
        for (int q = 0; q < 4; q++) {
            float4 a = w2[lane + 32 * q];
            float4 b = sI[lane + 32 * q];
            acc += a.x * b.x + a.y * b.y + a.z * b.z + a.w * b.w;
        }
        acc = warp_sum(acc);
        if (lane == 0) {
            g_win2[row] = acc;
            __threadfence();                 // publish win2
        }
        __syncthreads();
        if (tid == 0) {
            int old = atomicAdd(&g_done_w2, 1);
            if (old == W2_BLKS - 1) { g_done_w2 = 0; g_fw2 = 1; }   // release
        }
    } else if (bid < SETUP_BLKS + D_BLKS) {
        // ================= W_new rows (D GEMV + Hebbian) =================
        s_vec[tid]       = tanhf(z[tid]);
        s_vec[tid + 256] = tanhf(z[tid + 256]);
        __syncthreads();

        int p = (bid - SETUP_BLKS) * 8 + warp;
        const float4* dr = (const float4*)(D + (size_t)p * MM);
        const float4* ps = (const float4*)s_vec;
        float acc = 0.0f;
#pragma unroll
        for (int q = 0; q < 4; q++) {
            int idx = lane + 32 * q;       // 128 float4 per 512-float row
            float4 d = __ldcs(&dr[idx]);   // streaming: never reused
            float4 s = ps[idx];
            acc += d.x * s.x + d.y * s.y + d.z * s.z + d.w * s.w;
        }
        acc = warp_sum(acc);
        if (lane == 0) {
            if (g_fphi == 0) { while (g_fphi == 0) __nanosleep(32); }
            int i = p >> 8, j = p & 255;
            float ph = __ldcg(&g_phi[i]) * __ldcg(&g_phi[j]);  // L2-coherent
            out_W[p] = (1.0f - GAMMA) * W[p] + GAMMA * (C[p] * ph + acc);
        }
    } else {
        // ================= H@Phi partial sums + z tail combine =================
        if (tid == 0 && g_fphi == 0) { while (g_fphi == 0) __nanosleep(32); }
        __syncthreads();
        s_vec[tid] = __ldcg(&g_phi[tid]);   // fresh from L2
        __syncthreads();

        int b = bid - (SETUP_BLKS + D_BLKS);
        int c = b & (SPLIT - 1);  // chunk
        int m = b >> 4;           // row
        const float4* hr = (const float4*)(H + (size_t)m * NN2 + (size_t)c * CHUNK);

        float acc = 0.0f;
#pragma unroll
        for (int q = 0; q < 4; q++) {
            int f = tid + 256 * q;        // float4 index within chunk (0..1023)
            int p = c * CHUNK + f * 4;    // element index within row
            float4 h = __ldcs(&hr[f]);    // streaming: never reused
            int i = p >> 8;
            int j = p & 255;              // multiple of 4, j+3 <= 255
            float pi = s_vec[i];
            acc += pi * (h.x * s_vec[j] + h.y * s_vec[j + 1] +
                         h.z * s_vec[j + 2] + h.w * s_vec[j + 3]);
        }
        acc = warp_sum(acc);
        if (lane == 0) s_red[warp] = acc;
        __syncthreads();
        if (tid == 0) {
            float t = 0.0f;
#pragma unroll
            for (int w = 0; w < 8; w++) t += s_red[w];
            g_part[m * SPLIT + c] = t;
            __threadfence();                       // publish partial
            int old = atomicAdd(&g_cnt[m], 1);
            if (old == SPLIT - 1) {
                // last chunk of row m: combine (deterministic fixed order)
                g_cnt[m] = 0;                      // reset for next replay
                if (g_fw2 == 0) { while (g_fw2 == 0) __nanosleep(32); }
                float s = 0.0f;
#pragma unroll
                for (int c2 = 0; c2 < SPLIT; c2++)
                    s += __ldcg(&g_part[m * SPLIT + c2]);
                s += __ldcg(&g_win2[m]);
                float zm  = z[m];
                float psi = tanhf(zm);
                out_z[m] = (1.0f - GAMMA * TAU) * zm +
                           (GAMMA * TAU) * (F[m] * psi + s);
                int r = atomicAdd(&g_rows, 1);
                if (r == MM - 1) {                 // very last row: reset flags
                    g_rows = 0;
                    g_fphi = 0;
                    g_fw2  = 0;
                }
            }
        }
    }
}

// ---------------------------------------------------------------------------
// Launch: inputs in metadata order: I, x, W, z, C, D, F, H, W_in_1, W_in_2.
// Output: concat(x_new[256], W_new[65536], z_new[512]) = 66304 floats.
// ---------------------------------------------------------------------------
extern "C" void kernel_launch(void* const* d_in, const int* in_sizes, int n_in,
                              void* d_out, int out_size) {
    const float* I    = (const float*)d_in[0];
    const float* x    = (const float*)d_in[1];
    const float* W    = (const float*)d_in[2];
    const float* z    = (const float*)d_in[3];
    const float* C    = (const float*)d_in[4];
    const float* D    = (const float*)d_in[5];
    const float* F    = (const float*)d_in[6];
    const float* H    = (const float*)d_in[7];
    const float* Win1 = (const float*)d_in[8];
    const float* Win2 = (const float*)d_in[9];

    float* out_x = (float*)d_out;            // [0, 256)
    float* out_W = out_x + NN;               // [256, 256+65536)
    float* out_z = out_W + NN2;              // [65792, 66304)

    kBig<<<TOTAL_BLKS, 256>>>(x, W, Win1, I, Win2, C, D, z, H, F,
                              out_x, out_W, out_z);
}

// round 6
// speedup vs baseline: 1.2207x; 1.2207x over previous
#include <cuda_runtime.h>

// Problem constants
#define GAMMA 0.1f
#define TAU   0.01f
#define NN    256          // neuron count
#define MM    512          // astrocyte count
#define KK    512          // input dim
#define NN2   (NN * NN)    // 65536
#define SPLIT 16           // chunks per H row
#define CHUNK (NN2 / SPLIT) // 4096 floats per chunk

#define H_BLKS 8192
#define D_BLKS 8192

// Scratch (no allocations allowed in kernel_launch)
__device__ float g_phi[NN];           // sigmoid(x_new)
__device__ float g_part[MM * SPLIT];  // H@Phi partial sums
__device__ float g_win2[MM];          // W_in_2 @ I
__device__ int   g_cnt[MM];           // per-row H-chunk arrival counters (self-resetting)

__device__ __forceinline__ float warp_sum(float v) {
#pragma unroll
    for (int o = 16; o > 0; o >>= 1) v += __shfl_xor_sync(0xffffffffu, v, o);
    return v;
}

__device__ __forceinline__ float sigmoidf(float v) {
    return 1.0f / (1.0f + expf(-v));
}

// ---------------------------------------------------------------------------
// Kernel A: 768 blocks x 128 threads (block-per-row for max MLP).
//   blocks [0,256)   : x_new[row] + g_phi[row]
//   blocks [256,768) : g_win2[row] = (W_in_2 @ I)[row]
// Ends with cudaTriggerProgrammaticLaunchCompletion() to release kB's gridsync.
// ---------------------------------------------------------------------------
__global__ void __launch_bounds__(128) kA(
    const float* __restrict__ x,    const float* __restrict__ W,
    const float* __restrict__ Win1, const float* __restrict__ I,
    const float* __restrict__ Win2, float* __restrict__ out_x) {

    __shared__ float s_I[KK];
    __shared__ float s_phi[NN];
    __shared__ float s_red[4];
    int tid  = threadIdx.x;  // 128
    int warp = tid >> 5, lane = tid & 31;

    ((float4*)s_I)[tid] = ((const float4*)I)[tid];  // 128 float4 = 512 floats
    const float4* sI = (const float4*)s_I;

    float v;
    if (blockIdx.x < 256) {
        int row = blockIdx.x;
        s_phi[tid]       = sigmoidf(x[tid]);
        s_phi[tid + 128] = sigmoidf(x[tid + 128]);
        __syncthreads();

        float a1 = 0.0f, a2 = 0.0f;
        if (tid < 64) {  // W row: 256 floats = 64 float4
            float4 w = ((const float4*)(W + (size_t)row * NN))[tid];
            float4 p = ((const float4*)s_phi)[tid];
            a1 = w.x * p.x + w.y * p.y + w.z * p.z + w.w * p.w;
        }
        {   // Win1 row: 512 floats = 128 float4
            float4 a = ((const float4*)(Win1 + (size_t)row * KK))[tid];
            float4 b = sI[tid];
            a2 = a.x * b.x + a.y * b.y + a.z * b.z + a.w * b.w;
        }
        v = GAMMA * a1 + a2;
    } else {
        __syncthreads();
        int row = blockIdx.x - 256;  // 0..511
        float4 a = ((const float4*)(Win2 + (size_t)row * KK))[tid];
        float4 b = sI[tid];
        v = a.x * b.x + a.y * b.y + a.z * b.z + a.w * b.w;
    }

    v = warp_sum(v);
    if (lane == 0) s_red[warp] = v;
    __syncthreads();
    if (tid == 0) {
        float t = s_red[0] + s_red[1] + s_red[2] + s_red[3];
        if (blockIdx.x < 256) {
            int row = blockIdx.x;
            float xn = (1.0f - GAMMA) * x[row] + t;
            out_x[row] = xn;
            g_phi[row] = sigmoidf(xn);
        } else {
            g_win2[blockIdx.x - 256] = t;
        }
        __threadfence();  // publish before trigger (belt-and-suspenders)
    }
    __syncthreads();
    cudaTriggerProgrammaticLaunchCompletion();
}

// ---------------------------------------------------------------------------
// Kernel B: 16384 blocks x 256 threads (PDL secondary — may start before kA
// finishes; consumers of g_phi/g_win2 call cudaGridDependencySynchronize()).
//   blocks [0, 8192)     : H@Phi partial sums; LAST chunk block per row also
//                          combines the 16 partials + win2 into z_new (tail).
//   blocks [8192, 16384) : W_new rows (D GEMV + Hebbian; phi needed only in
//                          the epilogue, after the 16 KB stream).
// ---------------------------------------------------------------------------
__global__ void __launch_bounds__(256) kB(
    const float* __restrict__ W, const float* __restrict__ C,
    const float* __restrict__ D, const float* __restrict__ z,
    const float* __restrict__ H, const float* __restrict__ F,
    float* __restrict__ out_W, float* __restrict__ out_z) {

    __shared__ float s_vec[MM];
    __shared__ float s_red[8];
    int tid  = threadIdx.x;  // 256
    int warp = tid >> 5, lane = tid & 31;
    unsigned bid = blockIdx.x;

    if (bid < H_BLKS) {
        // ================= H@Phi partial sums + tail combine =================
        cudaGridDependencySynchronize();   // wait for kA's g_phi / g_win2
        s_vec[tid] = g_phi[tid];
        __syncthreads();

        int c = bid & (SPLIT - 1);  // chunk
        int m = bid >> 4;           // row
        const float4* hr = (const float4*)(H + (size_t)m * NN2 + (size_t)c * CHUNK);

        float acc = 0.0f;
#pragma unroll
        for (int q = 0; q < 4; q++) {
            int f = tid + 256 * q;        // float4 index within chunk (0..1023)
            int p = c * CHUNK + f * 4;    // element index within row
            float4 h = hr[f];
            int i = p >> 8;
            int j = p & 255;              // multiple of 4, j+3 <= 255
            float pi = s_vec[i];
            acc += pi * (h.x * s_vec[j] + h.y * s_vec[j + 1] +
                         h.z * s_vec[j + 2] + h.w * s_vec[j + 3]);
        }
        acc = warp_sum(acc);
        if (lane == 0) s_red[warp] = acc;
        __syncthreads();
        if (tid == 0) {
            float t = 0.0f;
#pragma unroll
            for (int w = 0; w < 8; w++) t += s_red[w];
            g_part[m * SPLIT + c] = t;
            __threadfence();                       // publish partial
            int old = atomicAdd(&g_cnt[m], 1);
            if (old == SPLIT - 1) {
                // last chunk of row m: combine (deterministic fixed order)
                g_cnt[m] = 0;                      // reset for next replay
                __threadfence();                   // acquire others' partials
                float s = 0.0f;
#pragma unroll
                for (int c2 = 0; c2 < SPLIT; c2++) s += g_part[m * SPLIT + c2];
                s += g_win2[m];
                float zm  = z[m];
                float psi = tanhf(zm);
                out_z[m] = (1.0f - GAMMA * TAU) * zm +
                           (GAMMA * TAU) * (F[m] * psi + s);
            }
        }
    } else {
        // ================= W_new rows (D GEMV + Hebbian) =================
        s_vec[tid]       = tanhf(z[tid]);
        s_vec[tid + 256] = tanhf(z[tid + 256]);
        __syncthreads();

        int p = (bid - H_BLKS) * 8 + warp;
        const float4* dr = (const float4*)(D + (size_t)p * MM);
        const float4* ps = (const float4*)s_vec;
        float acc = 0.0f;
#pragma unroll
        for (int q = 0; q < 4; q++) {
            int idx = lane + 32 * q;       // 128 float4 per 512-float row
            float4 d = dr[idx];
            float4 s = ps[idx];
            acc += d.x * s.x + d.y * s.y + d.z * s.z + d.w * s.w;
        }
        acc = warp_sum(acc);
        if (lane == 0) {
            cudaGridDependencySynchronize();   // phi ready (kA ended long ago)
            int i = p >> 8, j = p & 255;
            float ph = g_phi[i] * g_phi[j];
            out_W[p] = (1.0f - GAMMA) * W[p] + GAMMA * (C[p] * ph + acc);
        }
    }
}

// ---------------------------------------------------------------------------
// Launch: inputs in metadata order: I, x, W, z, C, D, F, H, W_in_1, W_in_2.
// Output: concat(x_new[256], W_new[65536], z_new[512]) = 66304 floats.
// kB is launched with programmatic stream serialization (PDL) so its blocks
// begin streaming D/H while kA is still in flight.
// ---------------------------------------------------------------------------
extern "C" void kernel_launch(void* const* d_in, const int* in_sizes, int n_in,
                              void* d_out, int out_size) {
    const float* I    = (const float*)d_in[0];
    const float* x    = (const float*)d_in[1];
    const float* W    = (const float*)d_in[2];
    const float* z    = (const float*)d_in[3];
    const float* C    = (const float*)d_in[4];
    const float* D    = (const float*)d_in[5];
    const float* F    = (const float*)d_in[6];
    const float* H    = (const float*)d_in[7];
    const float* Win1 = (const float*)d_in[8];
    const float* Win2 = (const float*)d_in[9];

    float* out_x = (float*)d_out;            // [0, 256)
    float* out_W = out_x + NN;               // [256, 256+65536)
    float* out_z = out_W + NN2;              // [65792, 66304)

    // Stage 1: x_new + phi + W_in_2@I
    kA<<<768, 128>>>(x, W, Win1, I, Win2, out_x);

    // Stage 2: fused H-partials (+ z_new tail combine) and W_new D-stream,
    // launched as a PDL secondary so it overlaps kA.
    {
        cudaLaunchAttribute attr[1];
        attr[0].id = cudaLaunchAttributeProgrammaticStreamSerialization;
        attr[0].val.programmaticStreamSerializationAllowed = 1;

        cudaLaunchConfig_t cfg = {};
        cfg.gridDim  = dim3(H_BLKS + D_BLKS, 1, 1);
        cfg.blockDim = dim3(256, 1, 1);
        cfg.dynamicSmemBytes = 0;
        cfg.stream = 0;   // legacy default stream (same as kA)
        cfg.attrs = attr;
        cfg.numAttrs = 1;

        cudaLaunchKernelEx(&cfg, kB, W, C, D, z, H, F, out_W, out_z);
    }
}

// round 7
// speedup vs baseline: 1.2270x; 1.0052x over previous
#include <cuda_runtime.h>

// Problem constants
#define GAMMA 0.1f
#define TAU   0.01f
#define NN    256          // neuron count
#define MM    512          // astrocyte count
#define KK    512          // input dim
#define NN2   (NN * NN)    // 65536
#define SPLIT 16           // chunks per H row
#define CHUNK (NN2 / SPLIT) // 4096 floats per chunk

#define H_BLKS 8192
#define D_BLKS 8192

// Scratch (no allocations allowed in kernel_launch)
__device__ float g_phi[NN];           // sigmoid(x_new)
__device__ float g_part[MM * SPLIT];  // H@Phi partial sums (chunk 0 includes win2)
__device__ int   g_cnt[MM];           // per-row H-chunk arrival counters (self-resetting)

__device__ __forceinline__ float warp_sum(float v) {
#pragma unroll
    for (int o = 16; o > 0; o >>= 1) v += __shfl_xor_sync(0xffffffffu, v, o);
    return v;
}

__device__ __forceinline__ float sigmoidf(float v) {
    return 1.0f / (1.0f + expf(-v));
}

// ---------------------------------------------------------------------------
// Kernel A (x-only): 256 blocks x 128 threads, block-per-row.
//   x_new[row] = (1-g)x[row] + g*(W[row,:]@sigmoid(x)) + Win1[row,:]@I
//   g_phi[row] = sigmoid(x_new[row])
// Total reads ~0.78 MB; high block count for latency hiding.
// ---------------------------------------------------------------------------
__global__ void __launch_bounds__(128) kA(
    const float* __restrict__ x,    const float* __restrict__ W,
    const float* __restrict__ Win1, const float* __restrict__ I,
    float* __restrict__ out_x) {

    __shared__ float s_phi[NN];
    __shared__ float s_red[4];
    int tid  = threadIdx.x;  // 128
    int warp = tid >> 5, lane = tid & 31;

    s_phi[tid]       = sigmoidf(x[tid]);
    s_phi[tid + 128] = sigmoidf(x[tid + 128]);
    __syncthreads();

    int row = blockIdx.x;
    float a1 = 0.0f, a2 = 0.0f;
    if (tid < 64) {  // W row: 256 floats = 64 float4
        float4 w = ((const float4*)(W + (size_t)row * NN))[tid];
        float4 p = ((const float4*)s_phi)[tid];
        a1 = w.x * p.x + w.y * p.y + w.z * p.z + w.w * p.w;
    }
    {   // Win1 row: 512 floats = 128 float4; I direct (L2-hot, 2 KB)
        float4 a = ((const float4*)(Win1 + (size_t)row * KK))[tid];
        float4 b = ((const float4*)I)[tid];
        a2 = a.x * b.x + a.y * b.y + a.z * b.z + a.w * b.w;
    }
    float v = GAMMA * a1 + a2;

    v = warp_sum(v);
    if (lane == 0) s_red[warp] = v;
    __syncthreads();
    if (tid == 0) {
        float t = s_red[0] + s_red[1] + s_red[2] + s_red[3];
        float xn = (1.0f - GAMMA) * x[row] + t;
        out_x[row] = xn;
        g_phi[row] = sigmoidf(xn);
    }
}

// ---------------------------------------------------------------------------
// Kernel B: 16384 blocks x 256 threads.
//   blocks [0, 8192)     : H@Phi partial sums. Chunk-0 blocks additionally add
//                          dot(Win2[m,:], I) to their partial. The LAST chunk
//                          block per row combines the 16 partials into z_new.
//   blocks [8192, 16384) : W_new rows (D GEMV + Hebbian; phi from kA).
// H blocks run first so their tail combines hide under the D stream.
// ---------------------------------------------------------------------------
__global__ void __launch_bounds__(256) kB(
    const float* __restrict__ W, const float* __restrict__ C,
    const float* __restrict__ D, const float* __restrict__ z,
    const float* __restrict__ H, const float* __restrict__ F,
    const float* __restrict__ Win2, const float* __restrict__ I,
    float* __restrict__ out_W, float* __restrict__ out_z) {

    __shared__ float s_vec[MM];
    __shared__ float s_red[8];
    int tid  = threadIdx.x;  // 256
    int warp = tid >> 5, lane = tid & 31;
    unsigned bid = blockIdx.x;

    if (bid < H_BLKS) {
        // ================= H@Phi partial sums (+win2 on chunk 0) =============
        s_vec[tid] = g_phi[tid];
        __syncthreads();

        int c = bid & (SPLIT - 1);  // chunk
        int m = bid >> 4;           // row
        const float4* hr = (const float4*)(H + (size_t)m * NN2 + (size_t)c * CHUNK);

        float acc = 0.0f;
#pragma unroll
        for (int q = 0; q < 4; q++) {
            int f = tid + 256 * q;        // float4 index within chunk (0..1023)
            int p = c * CHUNK + f * 4;    // element index within row
            float4 h = hr[f];
            int i = p >> 8;
            int j = p & 255;              // multiple of 4, j+3 <= 255
            float pi = s_vec[i];
            acc += pi * (h.x * s_vec[j] + h.y * s_vec[j + 1] +
                         h.z * s_vec[j + 2] + h.w * s_vec[j + 3]);
        }
        if (c == 0) {
            // fold (W_in_2 @ I)[m] into this chunk's partial (2 floats/thread)
            const float* w2 = Win2 + (size_t)m * KK;
            acc += w2[tid] * I[tid] + w2[tid + 256] * I[tid + 256];
        }
        acc = warp_sum(acc);
        if (lane == 0) s_red[warp] = acc;
        __syncthreads();
        if (tid == 0) {
            float t = 0.0f;
#pragma unroll
            for (int w = 0; w < 8; w++) t += s_red[w];
            g_part[m * SPLIT + c] = t;
            __threadfence();                       // publish partial
            int old = atomicAdd(&g_cnt[m], 1);
            if (old == SPLIT - 1) {
                // last chunk of row m: combine (deterministic fixed order)
                g_cnt[m] = 0;                      // reset for next replay
                __threadfence();                   // acquire others' partials
                float s = 0.0f;
#pragma unroll
                for (int c2 = 0; c2 < SPLIT; c2++) s += g_part[m * SPLIT + c2];
                float zm  = z[m];
                float psi = tanhf(zm);
                out_z[m] = (1.0f - GAMMA * TAU) * zm +
                           (GAMMA * TAU) * (F[m] * psi + s);
            }
        }
    } else {
        // ================= W_new rows (D GEMV + Hebbian) =================
        s_vec[tid]       = tanhf(z[tid]);
        s_vec[tid + 256] = tanhf(z[tid + 256]);
        __syncthreads();

        int p = (bid - H_BLKS) * 8 + warp;
        const float4* dr = (const float4*)(D + (size_t)p * MM);
        const float4* ps = (const float4*)s_vec;
        float acc = 0.0f;
#pragma unroll
        for (int q = 0; q < 4; q++) {
            int idx = lane + 32 * q;       // 128 float4 per 512-float row
            float4 d = dr[idx];
            float4 s = ps[idx];
            acc += d.x * s.x + d.y * s.y + d.z * s.z + d.w * s.w;
        }
        acc = warp_sum(acc);
        if (lane == 0) {
            int i = p >> 8, j = p & 255;
            float ph = g_phi[i] * g_phi[j];
            out_W[p] = (1.0f - GAMMA) * W[p] + GAMMA * (C[p] * ph + acc);
        }
    }
}

// ---------------------------------------------------------------------------
// Launch: inputs in metadata order: I, x, W, z, C, D, F, H, W_in_1, W_in_2.
// Output: concat(x_new[256], W_new[65536], z_new[512]) = 66304 floats.
// ---------------------------------------------------------------------------
extern "C" void kernel_launch(void* const* d_in, const int* in_sizes, int n_in,
                              void* d_out, int out_size) {
    const float* I    = (const float*)d_in[0];
    const float* x    = (const float*)d_in[1];
    const float* W    = (const float*)d_in[2];
    const float* z    = (const float*)d_in[3];
    const float* C    = (const float*)d_in[4];
    const float* D    = (const float*)d_in[5];
    const float* F    = (const float*)d_in[6];
    const float* H    = (const float*)d_in[7];
    const float* Win1 = (const float*)d_in[8];
    const float* Win2 = (const float*)d_in[9];

    float* out_x = (float*)d_out;            // [0, 256)
    float* out_W = out_x + NN;               // [256, 256+65536)
    float* out_z = out_W + NN2;              // [65792, 66304)

    // Stage 1: x_new + phi only (0.78 MB, 256 blocks)
    kA<<<NN, 128>>>(x, W, Win1, I, out_x);

    // Stage 2: fused H-partials (+win2 fold + z_new tail) and W_new D-stream
    kB<<<H_BLKS + D_BLKS, 256>>>(W, C, D, z, H, F, Win2, I, out_W, out_z);
}

// round 8
// speedup vs baseline: 1.2798x; 1.0430x over previous
#include <cuda_runtime.h>

// Problem constants
#define GAMMA 0.1f
#define TAU   0.01f
#define NN    256          // neuron count
#define MM    512          // astrocyte count
#define KK    512          // input dim
#define NN2   (NN * NN)    // 65536
#define SPLIT 8            // chunks per H row (32 KB each)
#define CHUNK (NN2 / SPLIT) // 8192 floats per chunk

#define H_BLKS (MM * SPLIT)        // 4096
#define D_ROWS_PER_BLK 16
#define D_BLKS (NN2 / D_ROWS_PER_BLK)  // 4096

// Scratch (no allocations allowed in kernel_launch)
__device__ float g_phi[NN];           // sigmoid(x_new)
__device__ float g_part[MM * SPLIT];  // H@Phi partial sums (chunk 0 includes win2)
__device__ int   g_cnt[MM];           // per-row H-chunk arrival counters (self-resetting)

__device__ __forceinline__ float warp_sum(float v) {
#pragma unroll
    for (int o = 16; o > 0; o >>= 1) v += __shfl_xor_sync(0xffffffffu, v, o);
    return v;
}

__device__ __forceinline__ float sigmoidf(float v) {
    return 1.0f / (1.0f + expf(-v));
}

// ---------------------------------------------------------------------------
// Kernel A (x-only): 256 blocks x 128 threads, block-per-row.
//   x_new[row] = (1-g)x[row] + g*(W[row,:]@sigmoid(x)) + Win1[row,:]@I
//   g_phi[row] = sigmoid(x_new[row])
// ---------------------------------------------------------------------------
__global__ void __launch_bounds__(128) kA(
    const float* __restrict__ x,    const float* __restrict__ W,
    const float* __restrict__ Win1, const float* __restrict__ I,
    float* __restrict__ out_x) {

    __shared__ float s_phi[NN];
    __shared__ float s_red[4];
    int tid  = threadIdx.x;  // 128
    int warp = tid >> 5, lane = tid & 31;

    s_phi[tid]       = sigmoidf(x[tid]);
    s_phi[tid + 128] = sigmoidf(x[tid + 128]);
    __syncthreads();

    int row = blockIdx.x;
    float a1 = 0.0f, a2 = 0.0f;
    if (tid < 64) {  // W row: 256 floats = 64 float4
        float4 w = ((const float4*)(W + (size_t)row * NN))[tid];
        float4 p = ((const float4*)s_phi)[tid];
        a1 = w.x * p.x + w.y * p.y + w.z * p.z + w.w * p.w;
    }
    {   // Win1 row: 512 floats = 128 float4; I direct (L2-hot, 2 KB)
        float4 a = ((const float4*)(Win1 + (size_t)row * KK))[tid];
        float4 b = ((const float4*)I)[tid];
        a2 = a.x * b.x + a.y * b.y + a.z * b.z + a.w * b.w;
    }
    float v = GAMMA * a1 + a2;

    v = warp_sum(v);
    if (lane == 0) s_red[warp] = v;
    __syncthreads();
    if (tid == 0) {
        float t = s_red[0] + s_red[1] + s_red[2] + s_red[3];
        float xn = (1.0f - GAMMA) * x[row] + t;
        out_x[row] = xn;
        g_phi[row] = sigmoidf(xn);
    }
}

// ---------------------------------------------------------------------------
// Kernel B: 8192 blocks x 256 threads. High-MLP grain (8 float4/thread).
//   blocks [0, 4096)     : H@Phi 32KB-chunk partials (chunk 0 folds Win2@I);
//                          LAST chunk block per row combines into z_new.
//   blocks [4096, 8192)  : W_new, 2 rows per warp (D GEMV + Hebbian).
// ---------------------------------------------------------------------------
__global__ void __launch_bounds__(256) kB(
    const float* __restrict__ W, const float* __restrict__ C,
    const float* __restrict__ D, const float* __restrict__ z,
    const float* __restrict__ H, const float* __restrict__ F,
    const float* __restrict__ Win2, const float* __restrict__ I,
    float* __restrict__ out_W, float* __restrict__ out_z) {

    __shared__ float s_vec[MM];
    __shared__ float s_red[8];
    int tid  = threadIdx.x;  // 256
    int warp = tid >> 5, lane = tid & 31;
    unsigned bid = blockIdx.x;

    if (bid < H_BLKS) {
        // ========== H@Phi partial sums, 32 KB/block (+win2 on chunk 0) =======
        s_vec[tid] = g_phi[tid];
        __syncthreads();

        int c = bid & (SPLIT - 1);  // chunk
        int m = bid >> 3;           // row
        const float4* hr = (const float4*)(H + (size_t)m * NN2 + (size_t)c * CHUNK);

        float4 h[8];
#pragma unroll
        for (int q = 0; q < 8; q++) h[q] = hr[tid + 256 * q];  // 8 in flight

        float acc = 0.0f;
#pragma unroll
        for (int q = 0; q < 8; q++) {
            int p = c * CHUNK + (tid + 256 * q) * 4;  // element index within row
            int i = p >> 8;
            int j = p & 255;              // multiple of 4, j+3 <= 255
            float pi = s_vec[i];
            acc += pi * (h[q].x * s_vec[j]     + h[q].y * s_vec[j + 1] +
                         h[q].z * s_vec[j + 2] + h[q].w * s_vec[j + 3]);
        }
        if (c == 0) {
            // fold (W_in_2 @ I)[m] into this chunk's partial (2 floats/thread)
            const float* w2 = Win2 + (size_t)m * KK;
            acc += w2[tid] * I[tid] + w2[tid + 256] * I[tid + 256];
        }
        acc = warp_sum(acc);
        if (lane == 0) s_red[warp] = acc;
        __syncthreads();
        if (tid == 0) {
            float t = 0.0f;
#pragma unroll
            for (int w = 0; w < 8; w++) t += s_red[w];
            g_part[m * SPLIT + c] = t;
            __threadfence();                       // publish partial
            int old = atomicAdd(&g_cnt[m], 1);
            if (old == SPLIT - 1) {
                // last chunk of row m: combine (deterministic fixed order)
                g_cnt[m] = 0;                      // reset for next replay
                __threadfence();                   // acquire others' partials
                float s = 0.0f;
#pragma unroll
                for (int c2 = 0; c2 < SPLIT; c2++) s += g_part[m * SPLIT + c2];
                float zm  = z[m];
                float psi = tanhf(zm);
                out_z[m] = (1.0f - GAMMA * TAU) * zm +
                           (GAMMA * TAU) * (F[m] * psi + s);
            }
        }
    } else {
        // ========== W_new: 2 rows per warp (D GEMV + Hebbian) ==========
        s_vec[tid]       = tanhf(z[tid]);
        s_vec[tid + 256] = tanhf(z[tid + 256]);
        __syncthreads();

        int p0 = (bid - H_BLKS) * D_ROWS_PER_BLK + warp * 2;  // rows p0, p0+1
        const float4* dr0 = (const float4*)(D + (size_t)p0 * MM);
        const float4* dr1 = (const float4*)(D + (size_t)(p0 + 1) * MM);
        const float4* ps  = (const float4*)s_vec;

        float4 a0[4], a1[4];
#pragma unroll
        for (int q = 0; q < 4; q++) a0[q] = dr0[lane + 32 * q];  // 8 loads
#pragma unroll
        for (int q = 0; q < 4; q++) a1[q] = dr1[lane + 32 * q];  // in flight

        float acc0 = 0.0f, acc1 = 0.0f;
#pragma unroll
        for (int q = 0; q < 4; q++) {
            float4 s = ps[lane + 32 * q];
            acc0 += a0[q].x * s.x + a0[q].y * s.y + a0[q].z * s.z + a0[q].w * s.w;
            acc1 += a1[q].x * s.x + a1[q].y * s.y + a1[q].z * s.z + a1[q].w * s.w;
        }
        acc0 = warp_sum(acc0);
        acc1 = warp_sum(acc1);
        if (lane == 0) {
            int i = p0 >> 8;                 // p0 even => same i for both rows
            int j0 = p0 & 255;
            float pi = g_phi[i];
            float ph0 = pi * g_phi[j0];
            float ph1 = pi * g_phi[j0 + 1];  // j0+1 <= 255 since p0 even
            out_W[p0]     = (1.0f - GAMMA) * W[p0]     + GAMMA * (C[p0]     * ph0 + acc0);
            out_W[p0 + 1] = (1.0f - GAMMA) * W[p0 + 1] + GAMMA * (C[p0 + 1] * ph1 + acc1);
        }
    }
}

// ---------------------------------------------------------------------------
// Launch: inputs in metadata order: I, x, W, z, C, D, F, H, W_in_1, W_in_2.
// Output: concat(x_new[256], W_new[65536], z_new[512]) = 66304 floats.
// ---------------------------------------------------------------------------
extern "C" void kernel_launch(void* const* d_in, const int* in_sizes, int n_in,
                              void* d_out, int out_size) {
    const float* I    = (const float*)d_in[0];
    const float* x    = (const float*)d_in[1];
    const float* W    = (const float*)d_in[2];
    const float* z    = (const float*)d_in[3];
    const float* C    = (const float*)d_in[4];
    const float* D    = (const float*)d_in[5];
    const float* F    = (const float*)d_in[6];
    const float* H    = (const float*)d_in[7];
    const float* Win1 = (const float*)d_in[8];
    const float* Win2 = (const float*)d_in[9];

    float* out_x = (float*)d_out;            // [0, 256)
    float* out_W = out_x + NN;               // [256, 256+65536)
    float* out_z = out_W + NN2;              // [65792, 66304)

    // Stage 1: x_new + phi only (0.78 MB, 256 blocks)
    kA<<<NN, 128>>>(x, W, Win1, I, out_x);

    // Stage 2: fused H-partials (+win2 fold + z_new tail) and W_new D-stream
    kB<<<H_BLKS + D_BLKS, 256>>>(W, C, D, z, H, F, Win2, I, out_W, out_z);
}